// round 12
// baseline (speedup 1.0000x reference)
#include <cuda_runtime.h>

#define BB_ 32
#define HH_ 12
#define CC_ 512
#define DD_ 768
#define EMB_ 768
#define NCLS_ 97
#define KIN_ 1542
#define KCORE_ 1536

// ---------------- scratch (device globals; no allocation) ----------------
__device__ float g_hs_t[DD_ * BB_];                     // logsumexp head emb [d][b]
__device__ float g_htp[BB_ * CC_];                      // pre-normalized ht_att (b,c)
__device__ float g_htsum[BB_ * 4];                      // 4 partial sums per batch
__device__ float g_rsp[16 * BB_ * DD_];                 // rs partials [chunk][b][d]
__device__ float g_rs_t[DD_ * BB_];                     // reduced rs [d][b]
__device__ float g_gp[2 * 24 * EMB_ * BB_];             // GEMM partials [side][ks][n][b]
__device__ float g_hsf_t[EMB_ * BB_];                   // tanh head features [n][b]
__device__ float g_tsf_t[EMB_ * BB_];                   // tanh tail features [n][b]
__device__ unsigned long long g_lp2[96 * 64 * 32];      // logits partials [ks][P][b]
__device__ unsigned g_cnt[4];                           // barrier counters (reset each use)
__device__ unsigned g_gen[4];                           // barrier generations (monotonic)

// ---------------- f32x2 helpers ----------------
__device__ __forceinline__ unsigned long long ffma2(unsigned long long a,
                                                    unsigned long long b,
                                                    unsigned long long c) {
    unsigned long long d;
    asm("fma.rn.f32x2 %0, %1, %2, %3;" : "=l"(d) : "l"(a), "l"(b), "l"(c));
    return d;
}
__device__ __forceinline__ unsigned long long pack2(float x) {
    unsigned long long r;
    asm("mov.b64 %0, {%1, %2};" : "=l"(r) : "f"(x), "f"(x));
    return r;
}
__device__ __forceinline__ unsigned long long packxy(float x, float y) {
    unsigned long long r;
    asm("mov.b64 %0, {%1, %2};" : "=l"(r) : "f"(x), "f"(y));
    return r;
}
__device__ __forceinline__ float2 unpack2(unsigned long long v) {
    float2 f;
    asm("mov.b64 {%0, %1}, %2;" : "=f"(f.x), "=f"(f.y) : "l"(v));
    return f;
}
__device__ __forceinline__ float hadd2(unsigned long long v) {
    float2 f = unpack2(v);
    return f.x + f.y;
}
__device__ __forceinline__ void cp_async8(unsigned dst, const void* src) {
    asm volatile("cp.async.ca.shared.global [%0], [%1], 8;\n" :: "r"(dst), "l"(src));
}

// Replay-safe grid barrier: counter resets to 0 every use; generation monotonic
// (absolute value never affects output). All nb CTAs must be co-resident.
__device__ __forceinline__ void grid_bar(int slot, unsigned nb) {
    __syncthreads();
    if (threadIdx.x == 0) {
        __threadfence();
        volatile unsigned* genp = &g_gen[slot];
        unsigned my = *genp;
        unsigned old = atomicAdd(&g_cnt[slot], 1u);
        if (old == nb - 1u) {
            g_cnt[slot] = 0u;
            __threadfence();
            atomicAdd(&g_gen[slot], 1u);
        } else {
            while (*genp == my) { __nanosleep(32); }
        }
        __threadfence();
    }
    __syncthreads();
}

// ================= K1: hs (logsumexp) + ht_att pre + partial sums =================
__global__ __launch_bounds__(384) void k1(const float* __restrict__ seq,
                                          const float* __restrict__ att,
                                          const int* __restrict__ ep) {
    int part = blockIdx.x, b = blockIdx.y, tid = threadIdx.x;
    int w = tid >> 5, lane = tid & 31;
    __shared__ int sp0[8], sp1[8];
    __shared__ float sacc[12][128];
    __shared__ float sred[12];
    if (tid < 16) {
        int side = tid >> 3, m = tid & 7;
        int p = ep[b * 16 + side * 8 + m] + 1;  // OFFSET
        if (side) sp1[m] = p; else sp0[m] = p;
    }
    __syncthreads();

    {
        const float* ab = att + ((size_t)(b * HH_ + w)) * CC_ * CC_;
        int c4 = part * 128 + lane * 4;
        float4 v0[8], v1[8];
        #pragma unroll
        for (int m = 0; m < 8; m++) {
            v0[m] = *(const float4*)(ab + (size_t)sp0[m] * CC_ + c4);
            v1[m] = *(const float4*)(ab + (size_t)sp1[m] * CC_ + c4);
        }
        float4 a0 = make_float4(0.f, 0.f, 0.f, 0.f);
        float4 a1 = make_float4(0.f, 0.f, 0.f, 0.f);
        #pragma unroll
        for (int m = 0; m < 8; m++) {
            a0.x += v0[m].x; a0.y += v0[m].y; a0.z += v0[m].z; a0.w += v0[m].w;
            a1.x += v1[m].x; a1.y += v1[m].y; a1.z += v1[m].z; a1.w += v1[m].w;
        }
        float4 pr = make_float4(a0.x * a1.x, a0.y * a1.y, a0.z * a1.z, a0.w * a1.w);
        *(float4*)&sacc[w][lane * 4] = pr;
    }
    __syncthreads();

    float pre = 0.f;
    if (tid < 128) {
        float s = 0.f;
        #pragma unroll
        for (int h = 0; h < 12; h++) s += sacc[h][tid];
        pre = s * (1.0f / 768.0f);
        g_htp[b * CC_ + part * 128 + tid] = pre;
    }
    #pragma unroll
    for (int o = 16; o > 0; o >>= 1) pre += __shfl_xor_sync(0xffffffffu, pre, o);
    if (lane == 0) sred[w] = pre;
    __syncthreads();
    if (tid == 0) {
        float s = 0.f;
        #pragma unroll
        for (int i = 0; i < 12; i++) s += sred[i];
        g_htsum[b * 4 + part] = s;
    }

    if (part < 2) {
        int d = part * 384 + tid;
        const float* sb = seq + (size_t)b * CC_ * DD_ + d;
        float v[8];
        #pragma unroll
        for (int m = 0; m < 8; m++) v[m] = sb[(size_t)sp0[m] * DD_];
        float mx = v[0];
        #pragma unroll
        for (int m = 1; m < 8; m++) mx = fmaxf(mx, v[m]);
        float s = 0.f;
        #pragma unroll
        for (int m = 0; m < 8; m++) s += expf(v[m] - mx);
        g_hs_t[d * BB_ + b] = mx + logf(s);
    }
}

// ================= K2: rs partials (50MB streaming read), explicit MLP=8 =================
__global__ __launch_bounds__(192) void k2(const float* __restrict__ seq) {
    int s = blockIdx.x, b = blockIdx.y, tid = threadIdx.x;
    __shared__ float sht[32];
    __shared__ float sinv;
    if (tid == 0) {
        float sm = g_htsum[b * 4] + g_htsum[b * 4 + 1] + g_htsum[b * 4 + 2] + g_htsum[b * 4 + 3];
        sinv = 1.0f / (sm + 1e-5f);
    }
    if (tid < 32) sht[tid] = g_htp[b * CC_ + s * 32 + tid];
    __syncthreads();

    const float4* sp = (const float4*)(seq + ((size_t)b * CC_ + s * 32) * DD_) + tid;
    float4 acc = make_float4(0.f, 0.f, 0.f, 0.f);
    #pragma unroll
    for (int g = 0; g < 4; g++) {
        float4 v[8];
        #pragma unroll
        for (int u = 0; u < 8; u++) v[u] = sp[(g * 8 + u) * 192];
        #pragma unroll
        for (int u = 0; u < 8; u++) {
            float wv = sht[g * 8 + u];
            acc.x += v[u].x * wv; acc.y += v[u].y * wv;
            acc.z += v[u].z * wv; acc.w += v[u].w * wv;
        }
    }
    float iv = sinv;
    acc.x *= iv; acc.y *= iv; acc.z *= iv; acc.w *= iv;
    ((float4*)(g_rsp + ((size_t)s * BB_ + b) * DD_))[tid] = acc;
}

// ================= KC: fused k2r + k3 (grid 576, 128 thr, 1 grid barrier) ========
// Phase A: collapse 16 rs partials -> g_rs_t (spread over all 73728 threads).
// Phase B: dual GEMM (12 nt x 24 ks x 2 side), identical to proven k3.
__global__ __launch_bounds__(128) void kc(const float* __restrict__ Wh,
                                          const float* __restrict__ Wt) {
    int bid = blockIdx.x, tid = threadIdx.x;

    // ---- Phase A: k2r over first 6144 threads ----
    {
        int gid = bid * 128 + tid;
        if (gid < 6144) {
            int b = gid / 192, q = gid - b * 192;
            const float4* src = (const float4*)(g_rsp + (size_t)b * DD_) + q;
            float4 acc = make_float4(0.f, 0.f, 0.f, 0.f);
            #pragma unroll
            for (int g = 0; g < 2; g++) {
                float4 v[8];
                #pragma unroll
                for (int u = 0; u < 8; u++) v[u] = src[(size_t)(g * 8 + u) * BB_ * DD_ / 4];
                #pragma unroll
                for (int u = 0; u < 8; u++) {
                    acc.x += v[u].x; acc.y += v[u].y; acc.z += v[u].z; acc.w += v[u].w;
                }
            }
            int d = q * 4;
            g_rs_t[(d + 0) * BB_ + b] = acc.x;
            g_rs_t[(d + 1) * BB_ + b] = acc.y;
            g_rs_t[(d + 2) * BB_ + b] = acc.z;
            g_rs_t[(d + 3) * BB_ + b] = acc.w;
        }
    }
    grid_bar(0, 576);

    // ---- Phase B: k3 ----
    int side = bid / 288;
    int rem = bid - side * 288;
    int ks = rem / 12, nt = rem - ks * 12;
    int tx = tid & 15, ty = tid >> 4;
    const float* W = side ? Wt : Wh;
    int n0 = nt * 64, k0 = ks * 64;

    __shared__ __align__(16) float w_s[64][66];                 // [n][k-pair*2]
    __shared__ __align__(16) unsigned long long x2_s[32][32];   // [kkp][b]

    #pragma unroll
    for (int t = 0; t < 16; t++) {
        int idx = tid + t * 128;          // 0..2047
        int n = idx >> 5, f2 = idx & 31;
        const float* src = W + (size_t)(n0 + n) * KIN_ + k0 + 2 * f2;
        unsigned dst = (unsigned)__cvta_generic_to_shared(&w_s[n][2 * f2]);
        cp_async8(dst, src);
    }
    asm volatile("cp.async.commit_group;\n" ::: "memory");

    {
        const float* gx = (k0 < 768) ? g_hs_t + (size_t)k0 * BB_
                                     : g_rs_t + (size_t)(k0 - 768) * BB_;
        #pragma unroll
        for (int t = 0; t < 8; t++) {
            int idx = tid + t * 128;          // 0..1023
            int kkp = idx >> 5, b = idx & 31;
            x2_s[kkp][b] = packxy(gx[(size_t)(2 * kkp) * BB_ + b],
                                  gx[(size_t)(2 * kkp + 1) * BB_ + b]);
        }
    }

    unsigned long long acc[4][4];
    #pragma unroll
    for (int i = 0; i < 4; i++)
        #pragma unroll
        for (int j = 0; j < 4; j++) acc[i][j] = 0ull;

    asm volatile("cp.async.wait_group 0;\n" ::: "memory");
    __syncthreads();

    #pragma unroll 4
    for (int kkp = 0; kkp < 32; kkp++) {
        unsigned long long w2[4], xb[4];
        #pragma unroll
        for (int i = 0; i < 4; i++)
            w2[i] = *(const unsigned long long*)&w_s[tx + 16 * i][2 * kkp];
        *(ulonglong2*)&xb[0] = *(const ulonglong2*)&x2_s[kkp][ty * 4];
        *(ulonglong2*)&xb[2] = *(const ulonglong2*)&x2_s[kkp][ty * 4 + 2];
        #pragma unroll
        for (int i = 0; i < 4; i++)
            #pragma unroll
            for (int j = 0; j < 4; j++)
                acc[i][j] = ffma2(w2[i], xb[j], acc[i][j]);
    }

    float* gp = g_gp + ((size_t)(side * 24 + ks)) * EMB_ * BB_;
    #pragma unroll
    for (int i = 0; i < 4; i++) {
        int n = n0 + tx + 16 * i;
        float4 r;
        r.x = hadd2(acc[i][0]);
        r.y = hadd2(acc[i][1]);
        r.z = hadd2(acc[i][2]);
        r.w = hadd2(acc[i][3]);
        *(float4*)&gp[(size_t)n * BB_ + ty * 4] = r;
    }
}

// ================= KD: fused k3r + k4 + k5 (grid 384, 128 thr, 2 grid barriers) ==
__global__ __launch_bounds__(128) void kd(const float* __restrict__ Wh,
                                          const float* __restrict__ Wt,
                                          const float* __restrict__ bh,
                                          const float* __restrict__ bt,
                                          const float* __restrict__ ner,
                                          const float* __restrict__ Wb,
                                          const float* __restrict__ bbil,
                                          float* __restrict__ out) {
    int bid = blockIdx.x, tid = threadIdx.x;

    // ---- Phase A: k3r — 49152 outputs over exactly 384*128 threads ----
    {
        int gid = bid * 128 + tid;
        int side = gid / (EMB_ * BB_);
        int rem = gid - side * EMB_ * BB_;
        int n = rem >> 5, bb = rem & 31;
        const float* gp = g_gp + (size_t)side * 24 * EMB_ * BB_ + rem;
        float s = 0.f;
        #pragma unroll
        for (int g = 0; g < 3; g++) {
            float v[8];
            #pragma unroll
            for (int u = 0; u < 8; u++) v[u] = gp[(size_t)(g * 8 + u) * EMB_ * BB_];
            v[0] += v[1]; v[2] += v[3]; v[4] += v[5]; v[6] += v[7];
            v[0] += v[2]; v[4] += v[6];
            s += v[0] + v[4];
        }
        const float* W = side ? Wt : Wh;
        #pragma unroll
        for (int j = 0; j < 6; j++)
            s += W[(size_t)n * KIN_ + KCORE_ + j] * ner[bb * 12 + side * 6 + j];
        s += (side ? bt : bh)[n];
        float* dst = side ? g_tsf_t : g_hsf_t;
        dst[n * BB_ + bb] = tanhf(s);
    }
    grid_bar(1, 384);

    // ---- Phase B: k4 ----
    {
        int nt = bid & 3, ks = bid >> 2;
        int tx = tid & 15, ty = tid >> 4;
        int n0 = nt * 32;

        __shared__ float sh[8][33], st[8][33];
        __shared__ float w_s[64][34];
        __shared__ __align__(16) unsigned long long x2_s[64][32];

        #pragma unroll
        for (int t = 0; t < 4; t++) {
            int idx = tid + t * 128;               // 0..511
            int half = idx >> 8;
            int loc = idx & 255;
            int v = loc >> 5, bb = loc & 31;
            float* dstm = half ? &st[0][0] : &sh[0][0];
            const float* srcm = half ? g_tsf_t : g_hsf_t;
            dstm[v * 33 + bb] = srcm[(ks * 8 + v) * BB_ + bb];
        }
        #pragma unroll
        for (int t = 0; t < 4; t++) {
            int idx = tid + t * 128;               // 0..511
            int n = idx >> 4;
            int kq = idx & 15;
            int nn = n0 + n;
            float4 v = (nn < NCLS_)
                ? *(const float4*)(Wb + (size_t)nn * 6144 + ks * 64 + kq * 4)
                : make_float4(0.f, 0.f, 0.f, 0.f);
            w_s[kq * 4 + 0][n] = v.x;
            w_s[kq * 4 + 1][n] = v.y;
            w_s[kq * 4 + 2][n] = v.z;
            w_s[kq * 4 + 3][n] = v.w;
        }
        __syncthreads();
        #pragma unroll
        for (int t = 0; t < 16; t++) {
            int idx = tid + t * 128;               // 0..2047
            int kk = idx >> 5, bb = idx & 31;
            int i = kk >> 3, j = kk & 7;
            x2_s[kk][bb] = pack2(sh[i][bb] * st[j][bb]);
        }
        __syncthreads();

        unsigned long long acc[4] = {0ull, 0ull, 0ull, 0ull};
        #pragma unroll 4
        for (int kk = 0; kk < 64; kk++) {
            unsigned long long w2 = *(const unsigned long long*)&w_s[kk][2 * tx];
            #pragma unroll
            for (int j = 0; j < 4; j++)
                acc[j] = ffma2(w2, x2_s[kk][ty * 4 + j], acc[j]);
        }
        int P = nt * 16 + tx;
        #pragma unroll
        for (int j = 0; j < 4; j++)
            g_lp2[((size_t)ks * 64 + P) * 32 + ty * 4 + j] = acc[j];
    }
    grid_bar(2, 384);

    // ---- Phase C: k5 ----
    {
        int gid = bid * 128 + tid;
        if (gid < BB_ * NCLS_) {
            int b = gid / NCLS_, n = gid - b * NCLS_;
            int P = n >> 1, c = n & 1;
            const float* lpf = (const float*)g_lp2;
            float s = bbil[n];
            #pragma unroll
            for (int g = 0; g < 12; g++) {
                float v[8];
                #pragma unroll
                for (int u = 0; u < 8; u++)
                    v[u] = lpf[((((size_t)(g * 8 + u)) * 64 + P) * 32 + b) * 2 + c];
                #pragma unroll
                for (int u = 0; u < 8; u++) s += v[u];
            }
            out[gid] = s;
        }
    }
}

extern "C" void kernel_launch(void* const* d_in, const int* in_sizes, int n_in,
                              void* d_out, int out_size) {
    const float* seq  = (const float*)d_in[0];
    const float* att  = (const float*)d_in[1];
    const float* ner  = (const float*)d_in[2];
    const float* Wh   = (const float*)d_in[3];
    const float* bh   = (const float*)d_in[4];
    const float* Wt   = (const float*)d_in[5];
    const float* bt   = (const float*)d_in[6];
    const float* Wb   = (const float*)d_in[7];
    const float* bbil = (const float*)d_in[8];
    const int*   ep   = (const int*)d_in[9];
    float* out = (float*)d_out;

    k1<<<dim3(4, 32), 384>>>(seq, att, ep);
    k2<<<dim3(16, 32), 192>>>(seq);
    kc<<<576, 128>>>(Wh, Wt);
    kd<<<384, 128>>>(Wh, Wt, bh, bt, ner, Wb, bbil, out);
}

// round 13
// speedup vs baseline: 1.0911x; 1.0911x over previous
#include <cuda_runtime.h>

#define BB_ 32
#define HH_ 12
#define CC_ 512
#define DD_ 768
#define EMB_ 768
#define NCLS_ 97
#define KIN_ 1542
#define KCORE_ 1536

// ---------------- scratch (device globals; no allocation) ----------------
__device__ float g_hs_t[DD_ * BB_];                     // logsumexp head emb [d][b]
__device__ float g_htp[BB_ * CC_];                      // pre-normalized ht_att (b,c)
__device__ float g_htsum[BB_ * 4];                      // 4 partial sums per batch
__device__ float g_rsp[16 * BB_ * DD_];                 // rs partials [chunk][b][d]
__device__ float g_rs_t[DD_ * BB_];                     // reduced rs [d][b]
__device__ float g_gp[2 * 24 * EMB_ * BB_];             // GEMM partials [side][ks][n][b]
__device__ float g_hsf_t[EMB_ * BB_];                   // tanh head features [n][b]
__device__ float g_tsf_t[EMB_ * BB_];                   // tanh tail features [n][b]
__device__ unsigned long long g_lp2[96 * 64 * 32];      // logits partials [ks][P][b]
__device__ unsigned g_k2cnt[BB_];                       // per-batch arrival counters (reset by reducer)

// ---------------- f32x2 helpers ----------------
__device__ __forceinline__ unsigned long long ffma2(unsigned long long a,
                                                    unsigned long long b,
                                                    unsigned long long c) {
    unsigned long long d;
    asm("fma.rn.f32x2 %0, %1, %2, %3;" : "=l"(d) : "l"(a), "l"(b), "l"(c));
    return d;
}
__device__ __forceinline__ unsigned long long pack2(float x) {
    unsigned long long r;
    asm("mov.b64 %0, {%1, %2};" : "=l"(r) : "f"(x), "f"(x));
    return r;
}
__device__ __forceinline__ unsigned long long packxy(float x, float y) {
    unsigned long long r;
    asm("mov.b64 %0, {%1, %2};" : "=l"(r) : "f"(x), "f"(y));
    return r;
}
__device__ __forceinline__ float2 unpack2(unsigned long long v) {
    float2 f;
    asm("mov.b64 {%0, %1}, %2;" : "=f"(f.x), "=f"(f.y) : "l"(v));
    return f;
}
__device__ __forceinline__ float hadd2(unsigned long long v) {
    float2 f = unpack2(v);
    return f.x + f.y;
}
__device__ __forceinline__ void cp_async8(unsigned dst, const void* src) {
    asm volatile("cp.async.ca.shared.global [%0], [%1], 8;\n" :: "r"(dst), "l"(src));
}
__device__ __forceinline__ float4 ldcg4(const float4* p) {
    float4 v;
    asm volatile("ld.global.cg.v4.f32 {%0,%1,%2,%3}, [%4];"
                 : "=f"(v.x), "=f"(v.y), "=f"(v.z), "=f"(v.w) : "l"(p));
    return v;
}

// ================= K1: hs (logsumexp) + ht_att pre + partial sums =================
__global__ __launch_bounds__(384) void k1(const float* __restrict__ seq,
                                          const float* __restrict__ att,
                                          const int* __restrict__ ep) {
    int part = blockIdx.x, b = blockIdx.y, tid = threadIdx.x;
    int w = tid >> 5, lane = tid & 31;
    __shared__ int sp0[8], sp1[8];
    __shared__ float sacc[12][128];
    __shared__ float sred[12];
    if (tid < 16) {
        int side = tid >> 3, m = tid & 7;
        int p = ep[b * 16 + side * 8 + m] + 1;  // OFFSET
        if (side) sp1[m] = p; else sp0[m] = p;
    }
    __syncthreads();

    {
        const float* ab = att + ((size_t)(b * HH_ + w)) * CC_ * CC_;
        int c4 = part * 128 + lane * 4;
        float4 v0[8], v1[8];
        #pragma unroll
        for (int m = 0; m < 8; m++) {
            v0[m] = *(const float4*)(ab + (size_t)sp0[m] * CC_ + c4);
            v1[m] = *(const float4*)(ab + (size_t)sp1[m] * CC_ + c4);
        }
        float4 a0 = make_float4(0.f, 0.f, 0.f, 0.f);
        float4 a1 = make_float4(0.f, 0.f, 0.f, 0.f);
        #pragma unroll
        for (int m = 0; m < 8; m++) {
            a0.x += v0[m].x; a0.y += v0[m].y; a0.z += v0[m].z; a0.w += v0[m].w;
            a1.x += v1[m].x; a1.y += v1[m].y; a1.z += v1[m].z; a1.w += v1[m].w;
        }
        float4 pr = make_float4(a0.x * a1.x, a0.y * a1.y, a0.z * a1.z, a0.w * a1.w);
        *(float4*)&sacc[w][lane * 4] = pr;
    }
    __syncthreads();

    float pre = 0.f;
    if (tid < 128) {
        float s = 0.f;
        #pragma unroll
        for (int h = 0; h < 12; h++) s += sacc[h][tid];
        pre = s * (1.0f / 768.0f);
        g_htp[b * CC_ + part * 128 + tid] = pre;
    }
    #pragma unroll
    for (int o = 16; o > 0; o >>= 1) pre += __shfl_xor_sync(0xffffffffu, pre, o);
    if (lane == 0) sred[w] = pre;
    __syncthreads();
    if (tid == 0) {
        float s = 0.f;
        #pragma unroll
        for (int i = 0; i < 12; i++) s += sred[i];
        g_htsum[b * 4 + part] = s;
    }

    if (part < 2) {
        int d = part * 384 + tid;
        const float* sb = seq + (size_t)b * CC_ * DD_ + d;
        float v[8];
        #pragma unroll
        for (int m = 0; m < 8; m++) v[m] = sb[(size_t)sp0[m] * DD_];
        float mx = v[0];
        #pragma unroll
        for (int m = 1; m < 8; m++) mx = fmaxf(mx, v[m]);
        float s = 0.f;
        #pragma unroll
        for (int m = 0; m < 8; m++) s += expf(v[m] - mx);
        g_hs_t[d * BB_ + b] = mx + logf(s);
    }
}

// ================= K2: rs partials (50MB stream, MLP=8) + last-CTA reduction =====
// grid (16, 32): x = c-chunk (32 rows), y = batch. 192 threads.
// The 16th-arriving CTA of each batch reduces that batch's 16 partials -> g_rs_t.
// Deterministic (fixed read order) and replay-safe (counter reset to 0 by reducer).
__global__ __launch_bounds__(192) void k2(const float* __restrict__ seq) {
    int s = blockIdx.x, b = blockIdx.y, tid = threadIdx.x;
    __shared__ float sht[32];
    __shared__ float sinv;
    __shared__ unsigned s_last;
    if (tid == 0) {
        float sm = g_htsum[b * 4] + g_htsum[b * 4 + 1] + g_htsum[b * 4 + 2] + g_htsum[b * 4 + 3];
        sinv = 1.0f / (sm + 1e-5f);
    }
    if (tid < 32) sht[tid] = g_htp[b * CC_ + s * 32 + tid];
    __syncthreads();

    const float4* sp = (const float4*)(seq + ((size_t)b * CC_ + s * 32) * DD_) + tid;
    float4 acc = make_float4(0.f, 0.f, 0.f, 0.f);
    #pragma unroll
    for (int g = 0; g < 4; g++) {
        float4 v[8];
        #pragma unroll
        for (int u = 0; u < 8; u++) v[u] = sp[(g * 8 + u) * 192];
        #pragma unroll
        for (int u = 0; u < 8; u++) {
            float wv = sht[g * 8 + u];
            acc.x += v[u].x * wv; acc.y += v[u].y * wv;
            acc.z += v[u].z * wv; acc.w += v[u].w * wv;
        }
    }
    float iv = sinv;
    acc.x *= iv; acc.y *= iv; acc.z *= iv; acc.w *= iv;
    ((float4*)(g_rsp + ((size_t)s * BB_ + b) * DD_))[tid] = acc;

    // ---- arrival protocol ----
    __syncthreads();                       // all partial writes issued
    if (tid == 0) {
        __threadfence();                   // make writes visible before count
        unsigned old = atomicAdd(&g_k2cnt[b], 1u);
        s_last = (old == 15u) ? 1u : 0u;
    }
    __syncthreads();
    if (s_last) {
        if (tid == 0) g_k2cnt[b] = 0u;     // reset for graph replay (only this CTA touches it now)
        __threadfence();                   // acquire: order partial reads after the count
        // reduce 16 chunks for batch b: 192 float4 columns, one per thread, MLP=16
        const float4* src = (const float4*)(g_rsp + (size_t)b * DD_) + tid;
        float4 v[16];
        #pragma unroll
        for (int u = 0; u < 16; u++)
            v[u] = ldcg4(src + (size_t)u * (BB_ * DD_ / 4));
        #pragma unroll
        for (int o = 8; o > 0; o >>= 1)
            #pragma unroll
            for (int u = 0; u < 8; u++)
                if (u < o) {
                    v[u].x += v[u + o].x; v[u].y += v[u + o].y;
                    v[u].z += v[u + o].z; v[u].w += v[u + o].w;
                }
        int d = tid * 4;
        g_rs_t[(d + 0) * BB_ + b] = v[0].x;
        g_rs_t[(d + 1) * BB_ + b] = v[0].y;
        g_rs_t[(d + 2) * BB_ + b] = v[0].z;
        g_rs_t[(d + 3) * BB_ + b] = v[0].w;
    }
}

// ================= K3: dual GEMM, 64k per CTA, high residency ====================
// grid (12, 24, 2): x = n-tile(64), y = k-split(64), z = side. 128 threads tx(16)xty(8).
__global__ __launch_bounds__(128) void k3(const float* __restrict__ Wh,
                                          const float* __restrict__ Wt) {
    int nt = blockIdx.x, ks = blockIdx.y, side = blockIdx.z;
    int tid = threadIdx.x, tx = tid & 15, ty = tid >> 4;
    const float* W = side ? Wt : Wh;
    int n0 = nt * 64, k0 = ks * 64;

    __shared__ __align__(16) float w_s[64][66];                 // [n][k-pair*2]
    __shared__ __align__(16) unsigned long long x2_s[32][32];   // [kkp][b]

    #pragma unroll
    for (int t = 0; t < 16; t++) {
        int idx = tid + t * 128;          // 0..2047
        int n = idx >> 5, f2 = idx & 31;  // f2 = k-pair
        const float* src = W + (size_t)(n0 + n) * KIN_ + k0 + 2 * f2;
        unsigned dst = (unsigned)__cvta_generic_to_shared(&w_s[n][2 * f2]);
        cp_async8(dst, src);
    }
    asm volatile("cp.async.commit_group;\n" ::: "memory");

    {
        const float* gx = (k0 < 768) ? g_hs_t + (size_t)k0 * BB_
                                     : g_rs_t + (size_t)(k0 - 768) * BB_;
        #pragma unroll
        for (int t = 0; t < 8; t++) {
            int idx = tid + t * 128;          // 0..1023
            int kkp = idx >> 5, b = idx & 31;
            x2_s[kkp][b] = packxy(gx[(size_t)(2 * kkp) * BB_ + b],
                                  gx[(size_t)(2 * kkp + 1) * BB_ + b]);
        }
    }

    unsigned long long acc[4][4];
    #pragma unroll
    for (int i = 0; i < 4; i++)
        #pragma unroll
        for (int j = 0; j < 4; j++) acc[i][j] = 0ull;

    asm volatile("cp.async.wait_group 0;\n" ::: "memory");
    __syncthreads();

    #pragma unroll 4
    for (int kkp = 0; kkp < 32; kkp++) {
        unsigned long long w2[4], xb[4];
        #pragma unroll
        for (int i = 0; i < 4; i++)
            w2[i] = *(const unsigned long long*)&w_s[tx + 16 * i][2 * kkp];
        *(ulonglong2*)&xb[0] = *(const ulonglong2*)&x2_s[kkp][ty * 4];
        *(ulonglong2*)&xb[2] = *(const ulonglong2*)&x2_s[kkp][ty * 4 + 2];
        #pragma unroll
        for (int i = 0; i < 4; i++)
            #pragma unroll
            for (int j = 0; j < 4; j++)
                acc[i][j] = ffma2(w2[i], xb[j], acc[i][j]);
    }

    float* gp = g_gp + ((size_t)(side * 24 + ks)) * EMB_ * BB_;
    #pragma unroll
    for (int i = 0; i < 4; i++) {
        int n = n0 + tx + 16 * i;
        float4 r;
        r.x = hadd2(acc[i][0]);
        r.y = hadd2(acc[i][1]);
        r.z = hadd2(acc[i][2]);
        r.w = hadd2(acc[i][3]);
        *(float4*)&gp[(size_t)n * BB_ + ty * 4] = r;
    }
}

// ================= K3r: reduce 24 k-partials (MLP=8 batches) + NER + bias + tanh ==
__global__ __launch_bounds__(256) void k3r(const float* __restrict__ Wh,
                                           const float* __restrict__ Wt,
                                           const float* __restrict__ bh,
                                           const float* __restrict__ bt,
                                           const float* __restrict__ ner) {
    int gid = blockIdx.x * 256 + threadIdx.x;
    int side = gid / (EMB_ * BB_);
    int rem = gid - side * EMB_ * BB_;
    int n = rem >> 5, bb = rem & 31;
    const float* gp = g_gp + (size_t)side * 24 * EMB_ * BB_ + rem;
    float s = 0.f;
    #pragma unroll
    for (int g = 0; g < 3; g++) {
        float v[8];
        #pragma unroll
        for (int u = 0; u < 8; u++) v[u] = gp[(size_t)(g * 8 + u) * EMB_ * BB_];
        v[0] += v[1]; v[2] += v[3]; v[4] += v[5]; v[6] += v[7];
        v[0] += v[2]; v[4] += v[6];
        s += v[0] + v[4];
    }
    const float* W = side ? Wt : Wh;
    #pragma unroll
    for (int j = 0; j < 6; j++)
        s += W[(size_t)n * KIN_ + KCORE_ + j] * ner[bb * 12 + side * 6 + j];
    s += (side ? bt : bh)[n];
    float* dst = side ? g_tsf_t : g_hsf_t;
    dst[n * BB_ + bb] = tanhf(s);
}

// ================= K4: bilinear + logits GEMM partials, f32x2 =================
__global__ __launch_bounds__(128) void k4(const float* __restrict__ Wb) {
    int nt = blockIdx.x, ks = blockIdx.y;
    int tid = threadIdx.x, tx = tid & 15, ty = tid >> 4;
    int n0 = nt * 32;

    __shared__ float sh[8][33], st[8][33];
    __shared__ float w_s[64][34];
    __shared__ __align__(16) unsigned long long x2_s[64][32];

    #pragma unroll
    for (int t = 0; t < 4; t++) {
        int idx = tid + t * 128;               // 0..511
        int half = idx >> 8;
        int loc = idx & 255;
        int v = loc >> 5, bb = loc & 31;
        float* dstm = half ? &st[0][0] : &sh[0][0];
        const float* srcm = half ? g_tsf_t : g_hsf_t;
        dstm[v * 33 + bb] = srcm[(ks * 8 + v) * BB_ + bb];
    }
    #pragma unroll
    for (int t = 0; t < 4; t++) {
        int idx = tid + t * 128;               // 0..511
        int n = idx >> 4;
        int kq = idx & 15;
        int nn = n0 + n;
        float4 v = (nn < NCLS_)
            ? *(const float4*)(Wb + (size_t)nn * 6144 + ks * 64 + kq * 4)
            : make_float4(0.f, 0.f, 0.f, 0.f);
        w_s[kq * 4 + 0][n] = v.x;
        w_s[kq * 4 + 1][n] = v.y;
        w_s[kq * 4 + 2][n] = v.z;
        w_s[kq * 4 + 3][n] = v.w;
    }
    __syncthreads();
    #pragma unroll
    for (int t = 0; t < 16; t++) {
        int idx = tid + t * 128;               // 0..2047
        int kk = idx >> 5, bb = idx & 31;
        int i = kk >> 3, j = kk & 7;
        x2_s[kk][bb] = pack2(sh[i][bb] * st[j][bb]);
    }
    __syncthreads();

    unsigned long long acc[4] = {0ull, 0ull, 0ull, 0ull};
    #pragma unroll 4
    for (int kk = 0; kk < 64; kk++) {
        unsigned long long w2 = *(const unsigned long long*)&w_s[kk][2 * tx];
        #pragma unroll
        for (int j = 0; j < 4; j++)
            acc[j] = ffma2(w2, x2_s[kk][ty * 4 + j], acc[j]);
    }
    int P = nt * 16 + tx;
    #pragma unroll
    for (int j = 0; j < 4; j++)
        g_lp2[((size_t)ks * 64 + P) * 32 + ty * 4 + j] = acc[j];
}

// ================= K5: final reduce + bias -> d_out =================
__global__ __launch_bounds__(256) void k5(const float* __restrict__ bbil,
                                          float* __restrict__ out) {
    int gid = blockIdx.x * 256 + threadIdx.x;
    if (gid < BB_ * NCLS_) {
        int b = gid / NCLS_, n = gid - b * NCLS_;
        int P = n >> 1, c = n & 1;
        const float* lpf = (const float*)g_lp2;
        float s = bbil[n];
        #pragma unroll
        for (int g = 0; g < 12; g++) {
            float v[8];
            #pragma unroll
            for (int u = 0; u < 8; u++)
                v[u] = lpf[((((size_t)(g * 8 + u)) * 64 + P) * 32 + b) * 2 + c];
            #pragma unroll
            for (int u = 0; u < 8; u++) s += v[u];
        }
        out[gid] = s;
    }
}

extern "C" void kernel_launch(void* const* d_in, const int* in_sizes, int n_in,
                              void* d_out, int out_size) {
    const float* seq  = (const float*)d_in[0];
    const float* att  = (const float*)d_in[1];
    const float* ner  = (const float*)d_in[2];
    const float* Wh   = (const float*)d_in[3];
    const float* bh   = (const float*)d_in[4];
    const float* Wt   = (const float*)d_in[5];
    const float* bt   = (const float*)d_in[6];
    const float* Wb   = (const float*)d_in[7];
    const float* bbil = (const float*)d_in[8];
    const int*   ep   = (const int*)d_in[9];
    float* out = (float*)d_out;

    k1<<<dim3(4, 32), 384>>>(seq, att, ep);
    k2<<<dim3(16, 32), 192>>>(seq);
    k3<<<dim3(12, 24, 2), 128>>>(Wh, Wt);
    k3r<<<192, 256>>>(Wh, Wt, bh, bt, ner);
    k4<<<dim3(4, 96), 128>>>(Wb);
    k5<<<13, 256>>>(bbil, out);
}